// round 10
// baseline (speedup 1.0000x reference)
#include <cuda_runtime.h>
#include <cuda_fp16.h>
#include <cstdint>

#define NT 256
#define LN_EPS 1e-5f

// smem byte offsets
#define SB_W1  0          // __half W1 packed: 64 cols x stride 80 halves  = 10240 B
#define SB_WB  10240      // __half Wbig packed: 72 cols x stride 208 halves = 29952 B
#define SB_BI  40192      // float b_init [64]
#define SB_BMX 40448      // float folded bias [65]+pad
#define SMEM_BYTES 40720

__device__ int    g_edges_is_i64;
__device__ __half g_w1[64 * 80];
__device__ __half g_wb[72 * 208];
__device__ float  g_bi[64];
__device__ float  g_bmx[68];

// N-permutation: logical frag col -> actual col (thread's 16 cols = 4 float4s)
__device__ __host__ __forceinline__ int sigp(int c) {
    return 16 * (c >> 4) + 4 * ((c & 7) >> 1) + 2 * ((c >> 3) & 1) + (c & 1);
}

__global__ void prep_all(const float* __restrict__ W_init,
                         const float* __restrict__ b_init,
                         const float* __restrict__ W_mlp,
                         const float* __restrict__ b_mlp,
                         const float* __restrict__ W_alpha,
                         const float* __restrict__ b_alpha,
                         const long long* __restrict__ e64)
{
    int i = blockIdx.x * blockDim.x + threadIdx.x;
    if (i == 0) {
        int ok = 1;
        for (int j = 0; j < 64; ++j) {
            long long v = e64[j];
            if (v < 0 || v >= (1LL << 31)) ok = 0;
        }
        g_edges_is_i64 = ok;
    }
    if (i < 64 * 64) {
        int c = i >> 6, k = i & 63;
        g_w1[c * 80 + k] = __float2half_rn(W_init[sigp(c) * 64 + k]);
    } else if (i < 64 * 64 + 72 * 192) {
        int j = i - 64 * 64;
        int c = j / 192, k = j - c * 192;
        float v = 0.f;
        if (c < 64) {
            int a = sigp(c);
            if (k < 64) {
                float s = 0.f;
                #pragma unroll 8
                for (int m = 0; m < 64; ++m) s += W_mlp[a * 192 + m] * W_init[m * 64 + k];
                v = s;
            } else v = W_mlp[a * 192 + k];
        } else if (c == 64) {
            if (k < 64) {
                float s = 0.f;
                #pragma unroll 8
                for (int m = 0; m < 64; ++m) s += W_alpha[m] * W_init[m * 64 + k];
                v = s;
            } else v = W_alpha[k];
        }
        g_wb[c * 208 + k] = __float2half_rn(v);
    } else if (i < 64 * 64 + 72 * 192 + 64) {
        int t = i - (64 * 64 + 72 * 192);
        g_bi[t] = b_init[t];
    } else if (i < 64 * 64 + 72 * 192 + 64 + 65) {
        int t = i - (64 * 64 + 72 * 192 + 64);
        float s = (t < 64) ? b_mlp[t] : b_alpha[0];
        const float* wr = (t < 64) ? (W_mlp + t * 192) : W_alpha;
        #pragma unroll 8
        for (int m = 0; m < 64; ++m) s += b_init[m] * wr[m];
        g_bmx[t] = s;
    }
}

__device__ __forceinline__ uint32_t H2(float a, float b) {
    __half2 h = __floats2half2_rn(a, b);
    return *(uint32_t*)&h;
}
__device__ __forceinline__ void mma_f16(float c[4], uint32_t a0, uint32_t a1, uint32_t a2,
                                        uint32_t a3, uint32_t b0, uint32_t b1) {
    asm volatile(
        "mma.sync.aligned.m16n8k16.row.col.f32.f16.f16.f32 "
        "{%0,%1,%2,%3}, {%4,%5,%6,%7}, {%8,%9}, {%0,%1,%2,%3};\n"
        : "+f"(c[0]), "+f"(c[1]), "+f"(c[2]), "+f"(c[3])
        : "r"(a0), "r"(a1), "r"(a2), "r"(a3), "r"(b0), "r"(b1));
}

__global__ void __launch_bounds__(NT)
edge_update_v10(const float* __restrict__ node_fts,
                const float* __restrict__ edge_fts,
                const void* __restrict__ edges_raw,
                float* __restrict__ out,
                int n_edges)
{
    extern __shared__ char smc[];
    const int tid = threadIdx.x;
    {
        int4* d = (int4*)smc;
        const int4* s1 = (const int4*)g_w1;
        for (int i = tid; i < 10240 / 16; i += NT) d[i] = s1[i];
        int4* d2 = (int4*)(smc + SB_WB);
        const int4* s2 = (const int4*)g_wb;
        for (int i = tid; i < 29952 / 16; i += NT) d2[i] = s2[i];
        float* bf = (float*)(smc + SB_BI);
        if (tid < 64) bf[tid] = g_bi[tid];
        float* bm = (float*)(smc + SB_BMX);
        if (tid < 65) bm[tid] = g_bmx[tid];
    }
    __syncthreads();

    const __half* sw1 = (const __half*)(smc + SB_W1);
    const __half* swb = (const __half*)(smc + SB_WB);
    const float*  sbi = (const float*)(smc + SB_BI);
    const float*  sbm = (const float*)(smc + SB_BMX);

    const int wid  = tid >> 5;
    const int lane = tid & 31;
    const int g_   = lane >> 3;          // unused placeholder (kept minimal)
    const int gq   = lane >> 2;          // quad id 0..7 (frag row within 8)
    const int t4   = lane & 3;
    const int is64 = g_edges_is_i64;
    const long long* e64 = (const long long*)edges_raw;
    const int*       e32 = (const int*)edges_raw;
    const float bma = sbm[64];

    const char* eB = (const char*)edge_fts;
    const char* nB = (const char*)node_fts;
    const int ntiles = (n_edges + 31) >> 5;

    for (int wt = blockIdx.x * 8 + wid; wt < ntiles; wt += gridDim.x * 8) {
        const int tb  = wt << 5;
        const int rem = min(32, n_edges - tb);

        // lane r holds row r's indices
        int hidx, tidx;
        {
            size_t ep = (size_t)min(tb + lane, n_edges - 1);
            if (is64) { hidx = (int)e64[ep]; tidx = (int)e64[ep + (size_t)n_edges]; }
            else      { hidx = e32[ep];      tidx = e32[ep + (size_t)n_edges]; }
        }
        // byte offsets (u32): [src][chunk], chunk r covers row r*8+gq
        uint32_t oA[3][4];
        #pragma unroll
        for (int r = 0; r < 4; ++r) {
            const int row = r * 8 + gq;
            const int er  = min(tb + row, n_edges - 1);
            oA[0][r] = (uint32_t)er * 256u + (uint32_t)(t4 * 16);
            const int hi = __shfl_sync(0xffffffffu, hidx, row);
            const int ti = __shfl_sync(0xffffffffu, tidx, row);
            oA[1][r] = (uint32_t)hi * 256u + (uint32_t)(t4 * 16);
            oA[2][r] = (uint32_t)ti * 256u + (uint32_t)(t4 * 16);
        }

        float accE[2][8][4], accB[2][9][4];
        #pragma unroll
        for (int a = 0; a < 2; ++a) {
            #pragma unroll
            for (int b = 0; b < 8; ++b)
                #pragma unroll
                for (int c = 0; c < 4; ++c) accE[a][b][c] = 0.f;
            #pragma unroll
            for (int b = 0; b < 9; ++b)
                #pragma unroll
                for (int c = 0; c < 4; ++c) accB[a][b][c] = 0.f;
        }

#define LDSTEP(D, sp) do { \
        const char* _b = ((sp) >= 4) ? nB : eB; \
        const uint32_t _o = (uint32_t)(((sp) & 3) * 64); \
        D[0] = __ldg((const float4*)(_b + oA[(sp) >> 2][0] + _o)); \
        D[1] = __ldg((const float4*)(_b + oA[(sp) >> 2][1] + _o)); \
        D[2] = __ldg((const float4*)(_b + oA[(sp) >> 2][2] + _o)); \
        D[3] = __ldg((const float4*)(_b + oA[(sp) >> 2][3] + _o)); \
    } while (0)

        float4 P0[4], P1[4];
        LDSTEP(P0, 0);
        LDSTEP(P1, 1);

        #pragma unroll
        for (int s = 0; s < 12; ++s) {
            float4* C = (s & 1) ? P1 : P0;
            uint32_t alo[4], ahi[4];
            #pragma unroll
            for (int r = 0; r < 4; ++r) {
                alo[r] = H2(C[r].x, C[r].y);
                ahi[r] = H2(C[r].z, C[r].w);
            }
            // prefetch s+2 into the buffer just consumed
            if (s < 10) {
                switch (s + 2) {
                    case 2:  LDSTEP(C, 2);  break;
                    case 3:  LDSTEP(C, 3);  break;
                    case 4:  LDSTEP(C, 4);  break;
                    case 5:  LDSTEP(C, 5);  break;
                    case 6:  LDSTEP(C, 6);  break;
                    case 7:  LDSTEP(C, 7);  break;
                    case 8:  LDSTEP(C, 8);  break;
                    case 9:  LDSTEP(C, 9);  break;
                    case 10: LDSTEP(C, 10); break;
                    default: LDSTEP(C, 11); break;
                }
            }
            const int ko = s * 16 + 4 * t4;
            #pragma unroll
            for (int nt = 0; nt < 9; ++nt) {
                uint2 w = *(const uint2*)&swb[(nt * 8 + gq) * 208 + ko];
                mma_f16(accB[0][nt], alo[0], alo[1], ahi[0], ahi[1], w.x, w.y);
                mma_f16(accB[1][nt], alo[2], alo[3], ahi[2], ahi[3], w.x, w.y);
            }
            if (s < 4) {
                #pragma unroll
                for (int nt = 0; nt < 8; ++nt) {
                    uint2 w = *(const uint2*)&sw1[(nt * 8 + gq) * 80 + ko];
                    mma_f16(accE[0][nt], alo[0], alo[1], ahi[0], ahi[1], w.x, w.y);
                    mma_f16(accE[1][nt], alo[2], alo[3], ahi[2], ahi[3], w.x, w.y);
                }
            }
        }
#undef LDSTEP

        // ---------------- epilogue ----------------
        #pragma unroll
        for (int mt = 0; mt < 2; ++mt)
        #pragma unroll
        for (int hf = 0; hf < 2; ++hf) {
            const int h2  = hf * 2;
            const int row = mt * 16 + hf * 8 + gq;

            float p[16], s1 = 0.f, s2 = 0.f;
            #pragma unroll
            for (int J = 0; J < 4; ++J) {
                float4 bm4 = *(const float4*)&sbm[J * 16 + t4 * 4];
                float pre[4] = { accB[mt][2 * J][h2]     + bm4.x,
                                 accB[mt][2 * J][h2 + 1] + bm4.y,
                                 accB[mt][2 * J + 1][h2]     + bm4.z,
                                 accB[mt][2 * J + 1][h2 + 1] + bm4.w };
                #pragma unroll
                for (int c = 0; c < 4; ++c) {
                    float th = 1.f - __fdividef(2.f, __expf(2.f * pre[c]) + 1.f);
                    p[J * 4 + c] = th;
                    s1 += th; s2 += th * th;
                }
            }
            s1 += __shfl_xor_sync(0xffffffffu, s1, 1);
            s1 += __shfl_xor_sync(0xffffffffu, s1, 2);
            s2 += __shfl_xor_sync(0xffffffffu, s2, 1);
            s2 += __shfl_xor_sync(0xffffffffu, s2, 2);
            float ap = accB[mt][8][h2] + bma;
            ap = __shfl_sync(0xffffffffu, ap, lane & ~3);
            const float alpha = __fdividef(1.f, 1.f + __expf(-ap));
            const float mean  = s1 * (1.f / 64.f);
            const float var   = s2 * (1.f / 64.f) - mean * mean;
            const float rstd  = rsqrtf(var + LN_EPS) * alpha;

            float y[16], u1 = 0.f, u2 = 0.f;
            #pragma unroll
            for (int J = 0; J < 4; ++J) {
                float4 bi4 = *(const float4*)&sbi[J * 16 + t4 * 4];
                float y0 = accE[mt][2 * J][h2]     + bi4.x + (p[J * 4 + 0] - mean) * rstd;
                float y1 = accE[mt][2 * J][h2 + 1] + bi4.y + (p[J * 4 + 1] - mean) * rstd;
                float y2 = accE[mt][2 * J + 1][h2]     + bi4.z + (p[J * 4 + 2] - mean) * rstd;
                float y3 = accE[mt][2 * J + 1][h2 + 1] + bi4.w + (p[J * 4 + 3] - mean) * rstd;
                y[J * 4 + 0] = y0; y[J * 4 + 1] = y1; y[J * 4 + 2] = y2; y[J * 4 + 3] = y3;
                u1 += y0 + y1 + y2 + y3;
                u2 += y0 * y0 + y1 * y1 + y2 * y2 + y3 * y3;
            }
            u1 += __shfl_xor_sync(0xffffffffu, u1, 1);
            u1 += __shfl_xor_sync(0xffffffffu, u1, 2);
            u2 += __shfl_xor_sync(0xffffffffu, u2, 1);
            u2 += __shfl_xor_sync(0xffffffffu, u2, 2);
            const float m2  = u1 * (1.f / 64.f);
            const float v2  = u2 * (1.f / 64.f) - m2 * m2;
            const float rs2 = rsqrtf(v2 + LN_EPS);

            if (row < rem) {
                float* op = out + (size_t)(tb + row) * 64;
                #pragma unroll
                for (int J = 0; J < 4; ++J) {
                    float4 o;
                    o.x = (y[J * 4 + 0] - m2) * rs2;
                    o.y = (y[J * 4 + 1] - m2) * rs2;
                    o.z = (y[J * 4 + 2] - m2) * rs2;
                    o.w = (y[J * 4 + 3] - m2) * rs2;
                    *(float4*)(op + J * 16 + t4 * 4) = o;
                }
            }
        }
    }
}

extern "C" void kernel_launch(void* const* d_in, const int* in_sizes, int n_in,
                              void* d_out, int out_size)
{
    const float* node_fts = (const float*)d_in[0];
    const float* edge_fts = (const float*)d_in[1];
    const void*  edges    = d_in[2];
    const float* W_init   = (const float*)d_in[3];
    const float* b_init   = (const float*)d_in[4];
    const float* W_mlp    = (const float*)d_in[5];
    const float* b_mlp    = (const float*)d_in[6];
    const float* W_alpha  = (const float*)d_in[7];
    const float* b_alpha  = (const float*)d_in[8];
    float*       out      = (float*)d_out;

    const int n_edges = in_sizes[1] / 64;
    const int ntiles  = (n_edges + 31) / 32;

    int nsm = 148;
    cudaDeviceGetAttribute(&nsm, cudaDevAttrMultiProcessorCount, 0);
    int need = (ntiles + 7) / 8;
    int grid = need < nsm ? need : nsm;

    cudaFuncSetAttribute(edge_update_v10,
                         cudaFuncAttributeMaxDynamicSharedMemorySize, SMEM_BYTES);
    prep_all<<<74, 256>>>(W_init, b_init, W_mlp, b_mlp, W_alpha, b_alpha,
                          (const long long*)edges);
    edge_update_v10<<<grid, NT, SMEM_BYTES>>>(node_fts, edge_fts, edges, out, n_edges);
}

// round 11
// speedup vs baseline: 1.0604x; 1.0604x over previous
#include <cuda_runtime.h>
#include <cuda_fp16.h>
#include <cstdint>

#define NT 256
#define LN_EPS 1e-5f
#define MAX_NODES 100000

// smem byte offsets
#define SB_W1  0          // __half W1 packed: 64 cols x stride 80 halves  = 10240 B
#define SB_WB  10240      // __half Wbig packed: 72 cols x stride 208 halves = 29952 B
#define SB_BI  40192      // float b_init [64]
#define SB_BMX 40448      // float folded bias [65]+pad
#define SMEM_BYTES 40720

__device__ int    g_edges_is_i64;
__device__ __half g_w1[64 * 80];
__device__ __half g_wb[72 * 208];
__device__ float  g_bi[64];
__device__ float  g_bmx[68];
__device__ __half g_nodeh[MAX_NODES * 64];   // 12.8 MB fp16 node cache

// N-permutation: logical frag col -> actual col (thread's 16 cols = 4 float4s)
__device__ __host__ __forceinline__ int sigp(int c) {
    return 16 * (c >> 4) + 4 * ((c & 7) >> 1) + 2 * ((c >> 3) & 1) + (c & 1);
}

__global__ void prep_all(const float* __restrict__ W_init,
                         const float* __restrict__ b_init,
                         const float* __restrict__ W_mlp,
                         const float* __restrict__ b_mlp,
                         const float* __restrict__ W_alpha,
                         const float* __restrict__ b_alpha,
                         const long long* __restrict__ e64)
{
    int i = blockIdx.x * blockDim.x + threadIdx.x;
    if (i == 0) {
        int ok = 1;
        for (int j = 0; j < 64; ++j) {
            long long v = e64[j];
            if (v < 0 || v >= (1LL << 31)) ok = 0;
        }
        g_edges_is_i64 = ok;
    }
    if (i < 64 * 64) {
        int c = i >> 6, k = i & 63;
        g_w1[c * 80 + k] = __float2half_rn(W_init[sigp(c) * 64 + k]);
    } else if (i < 64 * 64 + 72 * 192) {
        int j = i - 64 * 64;
        int c = j / 192, k = j - c * 192;
        float v = 0.f;
        if (c < 64) {
            int a = sigp(c);
            if (k < 64) {
                float s = 0.f;
                #pragma unroll 8
                for (int m = 0; m < 64; ++m) s += W_mlp[a * 192 + m] * W_init[m * 64 + k];
                v = s;
            } else v = W_mlp[a * 192 + k];
        } else if (c == 64) {
            if (k < 64) {
                float s = 0.f;
                #pragma unroll 8
                for (int m = 0; m < 64; ++m) s += W_alpha[m] * W_init[m * 64 + k];
                v = s;
            } else v = W_alpha[k];
        }
        g_wb[c * 208 + k] = __float2half_rn(v);
    } else if (i < 64 * 64 + 72 * 192 + 64) {
        int t = i - (64 * 64 + 72 * 192);
        g_bi[t] = b_init[t];
    } else if (i < 64 * 64 + 72 * 192 + 64 + 65) {
        int t = i - (64 * 64 + 72 * 192 + 64);
        float s = (t < 64) ? b_mlp[t] : b_alpha[0];
        const float* wr = (t < 64) ? (W_mlp + t * 192) : W_alpha;
        #pragma unroll 8
        for (int m = 0; m < 64; ++m) s += b_init[m] * wr[m];
        g_bmx[t] = s;
    }
}

// convert node features to fp16 (rn) — identical values to in-kernel conversion
__global__ void prep_node(const float* __restrict__ node_fts, int n4)
{
    int i = blockIdx.x * blockDim.x + threadIdx.x;
    if (i < n4) {
        float4 v = __ldg((const float4*)node_fts + i);
        __half2 h0 = __floats2half2_rn(v.x, v.y);
        __half2 h1 = __floats2half2_rn(v.z, v.w);
        uint2 u = { *(uint32_t*)&h0, *(uint32_t*)&h1 };
        *((uint2*)g_nodeh + i) = u;
    }
}

__device__ __forceinline__ uint32_t H2(float a, float b) {
    __half2 h = __floats2half2_rn(a, b);
    return *(uint32_t*)&h;
}
__device__ __forceinline__ void mma_f16(float c[4], uint32_t a0, uint32_t a1, uint32_t a2,
                                        uint32_t a3, uint32_t b0, uint32_t b1) {
    asm volatile(
        "mma.sync.aligned.m16n8k16.row.col.f32.f16.f16.f32 "
        "{%0,%1,%2,%3}, {%4,%5,%6,%7}, {%8,%9}, {%0,%1,%2,%3};\n"
        : "+f"(c[0]), "+f"(c[1]), "+f"(c[2]), "+f"(c[3])
        : "r"(a0), "r"(a1), "r"(a2), "r"(a3), "r"(b0), "r"(b1));
}

__global__ void __launch_bounds__(NT, 2)
edge_update_v11(const float* __restrict__ edge_fts,
                const void* __restrict__ edges_raw,
                float* __restrict__ out,
                int n_edges)
{
    extern __shared__ char smc[];
    const int tid = threadIdx.x;
    {
        int4* d = (int4*)smc;
        const int4* s1 = (const int4*)g_w1;
        for (int i = tid; i < 10240 / 16; i += NT) d[i] = s1[i];
        int4* d2 = (int4*)(smc + SB_WB);
        const int4* s2 = (const int4*)g_wb;
        for (int i = tid; i < 29952 / 16; i += NT) d2[i] = s2[i];
        float* bf = (float*)(smc + SB_BI);
        if (tid < 64) bf[tid] = g_bi[tid];
        float* bm = (float*)(smc + SB_BMX);
        if (tid < 65) bm[tid] = g_bmx[tid];
    }
    __syncthreads();

    const __half* sw1 = (const __half*)(smc + SB_W1);
    const __half* swb = (const __half*)(smc + SB_WB);
    const float*  sbi = (const float*)(smc + SB_BI);
    const float*  sbm = (const float*)(smc + SB_BMX);

    const int wid  = tid >> 5;
    const int lane = tid & 31;
    const int gq   = lane >> 2;
    const int t4   = lane & 3;
    const int is64 = g_edges_is_i64;
    const long long* e64 = (const long long*)edges_raw;
    const int*       e32 = (const int*)edges_raw;
    const float bma = sbm[64];

    const char* eB = (const char*)edge_fts;
    const char* nH = (const char*)g_nodeh;
    const int ntiles = (n_edges + 15) >> 4;

    for (int wt = blockIdx.x * 8 + wid; wt < ntiles; wt += gridDim.x * 8) {
        const int tb  = wt << 4;
        const int rem = min(16, n_edges - tb);

        int hidx = 0, tidx = 0;
        if (lane < 16) {
            size_t ep = (size_t)min(tb + lane, n_edges - 1);
            if (is64) { hidx = (int)e64[ep]; tidx = (int)e64[ep + (size_t)n_edges]; }
            else      { hidx = e32[ep];      tidx = e32[ep + (size_t)n_edges]; }
        }
        // edge offsets (fp32, 256B rows) and node offsets (fp16, 128B rows)
        const char* pE[2];
        uint32_t oN[2][2];                     // [head/tail][row-chunk]
        #pragma unroll
        for (int r = 0; r < 2; ++r) {
            const int row = r * 8 + gq;
            const int er  = min(tb + row, n_edges - 1);
            pE[r] = eB + (size_t)er * 256 + (size_t)(t4 * 16);
            const int hi = __shfl_sync(0xffffffffu, hidx, row);
            const int ti = __shfl_sync(0xffffffffu, tidx, row);
            oN[0][r] = (uint32_t)hi * 128u + (uint32_t)(t4 * 8);
            oN[1][r] = (uint32_t)ti * 128u + (uint32_t)(t4 * 8);
        }

        float accE[8][4], accB[9][4];
        #pragma unroll
        for (int b = 0; b < 8; ++b)
            #pragma unroll
            for (int c = 0; c < 4; ++c) accE[b][c] = 0.f;
        #pragma unroll
        for (int b = 0; b < 9; ++b)
            #pragma unroll
            for (int c = 0; c < 4; ++c) accB[b][c] = 0.f;

        // -------- edge phase: s = 0..3 (fp32 load + cvt), both GEMMs --------
        float4 vc0 = __ldg((const float4*)pE[0]);
        float4 vc1 = __ldg((const float4*)pE[1]);
        uint2 nc0, nc1;                        // first node step preload
        #pragma unroll
        for (int s = 0; s < 4; ++s) {
            float4 vn0, vn1;
            if (s < 3) {
                vn0 = __ldg((const float4*)(pE[0] + (s + 1) * 64));
                vn1 = __ldg((const float4*)(pE[1] + (s + 1) * 64));
            } else {
                nc0 = __ldg((const uint2*)(nH + oN[0][0]));
                nc1 = __ldg((const uint2*)(nH + oN[0][1]));
            }
            const uint32_t a0 = H2(vc0.x, vc0.y), a1 = H2(vc1.x, vc1.y);
            const uint32_t a2 = H2(vc0.z, vc0.w), a3 = H2(vc1.z, vc1.w);
            const int ko = s * 16 + 4 * t4;
            #pragma unroll
            for (int nt = 0; nt < 9; ++nt) {
                uint2 w = *(const uint2*)&swb[(nt * 8 + gq) * 208 + ko];
                mma_f16(accB[nt], a0, a1, a2, a3, w.x, w.y);
            }
            #pragma unroll
            for (int nt = 0; nt < 8; ++nt) {
                uint2 w = *(const uint2*)&sw1[(nt * 8 + gq) * 80 + ko];
                mma_f16(accE[nt], a0, a1, a2, a3, w.x, w.y);
            }
            if (s < 3) { vc0 = vn0; vc1 = vn1; }
        }
        // -------- node phase: s = 4..11 (fp16 direct), big GEMM only --------
        #pragma unroll
        for (int s4 = 0; s4 < 8; ++s4) {
            uint2 nn0, nn1;
            if (s4 < 7) {
                const int sp = s4 + 1;
                nn0 = __ldg((const uint2*)(nH + oN[sp >> 2][0] + (sp & 3) * 32));
                nn1 = __ldg((const uint2*)(nH + oN[sp >> 2][1] + (sp & 3) * 32));
            }
            const int ko = (s4 + 4) * 16 + 4 * t4;
            #pragma unroll
            for (int nt = 0; nt < 9; ++nt) {
                uint2 w = *(const uint2*)&swb[(nt * 8 + gq) * 208 + ko];
                mma_f16(accB[nt], nc0.x, nc1.x, nc0.y, nc1.y, w.x, w.y);
            }
            if (s4 < 7) { nc0 = nn0; nc1 = nn1; }
        }

        // ---------------- epilogue (registers only) ----------------
        #pragma unroll
        for (int hf = 0; hf < 2; ++hf) {
            const int h2  = hf * 2;
            const int row = hf * 8 + gq;

            float p[16], s1 = 0.f, s2 = 0.f;
            #pragma unroll
            for (int J = 0; J < 4; ++J) {
                float4 bm4 = *(const float4*)&sbm[J * 16 + t4 * 4];
                float pre[4] = { accB[2 * J][h2]     + bm4.x,
                                 accB[2 * J][h2 + 1] + bm4.y,
                                 accB[2 * J + 1][h2]     + bm4.z,
                                 accB[2 * J + 1][h2 + 1] + bm4.w };
                #pragma unroll
                for (int c = 0; c < 4; ++c) {
                    float th = 1.f - __fdividef(2.f, __expf(2.f * pre[c]) + 1.f);
                    p[J * 4 + c] = th;
                    s1 += th; s2 += th * th;
                }
            }
            s1 += __shfl_xor_sync(0xffffffffu, s1, 1);
            s1 += __shfl_xor_sync(0xffffffffu, s1, 2);
            s2 += __shfl_xor_sync(0xffffffffu, s2, 1);
            s2 += __shfl_xor_sync(0xffffffffu, s2, 2);
            float ap = accB[8][h2] + bma;
            ap = __shfl_sync(0xffffffffu, ap, lane & ~3);
            const float alpha = __fdividef(1.f, 1.f + __expf(-ap));
            const float mean  = s1 * (1.f / 64.f);
            const float var   = s2 * (1.f / 64.f) - mean * mean;
            const float rstd  = rsqrtf(var + LN_EPS) * alpha;

            float y[16], u1 = 0.f, u2 = 0.f;
            #pragma unroll
            for (int J = 0; J < 4; ++J) {
                float4 bi4 = *(const float4*)&sbi[J * 16 + t4 * 4];
                float y0 = accE[2 * J][h2]     + bi4.x + (p[J * 4 + 0] - mean) * rstd;
                float y1 = accE[2 * J][h2 + 1] + bi4.y + (p[J * 4 + 1] - mean) * rstd;
                float y2 = accE[2 * J + 1][h2]     + bi4.z + (p[J * 4 + 2] - mean) * rstd;
                float y3 = accE[2 * J + 1][h2 + 1] + bi4.w + (p[J * 4 + 3] - mean) * rstd;
                y[J * 4 + 0] = y0; y[J * 4 + 1] = y1; y[J * 4 + 2] = y2; y[J * 4 + 3] = y3;
                u1 += y0 + y1 + y2 + y3;
                u2 += y0 * y0 + y1 * y1 + y2 * y2 + y3 * y3;
            }
            u1 += __shfl_xor_sync(0xffffffffu, u1, 1);
            u1 += __shfl_xor_sync(0xffffffffu, u1, 2);
            u2 += __shfl_xor_sync(0xffffffffu, u2, 1);
            u2 += __shfl_xor_sync(0xffffffffu, u2, 2);
            const float m2  = u1 * (1.f / 64.f);
            const float v2  = u2 * (1.f / 64.f) - m2 * m2;
            const float rs2 = rsqrtf(v2 + LN_EPS);

            if (row < rem) {
                float* op = out + (size_t)(tb + row) * 64;
                #pragma unroll
                for (int J = 0; J < 4; ++J) {
                    float4 o;
                    o.x = (y[J * 4 + 0] - m2) * rs2;
                    o.y = (y[J * 4 + 1] - m2) * rs2;
                    o.z = (y[J * 4 + 2] - m2) * rs2;
                    o.w = (y[J * 4 + 3] - m2) * rs2;
                    __stcs((float4*)(op + J * 16 + t4 * 4), o);
                }
            }
        }
    }
}

extern "C" void kernel_launch(void* const* d_in, const int* in_sizes, int n_in,
                              void* d_out, int out_size)
{
    const float* node_fts = (const float*)d_in[0];
    const float* edge_fts = (const float*)d_in[1];
    const void*  edges    = d_in[2];
    const float* W_init   = (const float*)d_in[3];
    const float* b_init   = (const float*)d_in[4];
    const float* W_mlp    = (const float*)d_in[5];
    const float* b_mlp    = (const float*)d_in[6];
    const float* W_alpha  = (const float*)d_in[7];
    const float* b_alpha  = (const float*)d_in[8];
    float*       out      = (float*)d_out;

    const int n_edges = in_sizes[1] / 64;
    const int n_node4 = in_sizes[0] / 4;       // float4 count of node_fts
    const int ntiles  = (n_edges + 15) / 16;

    int nsm = 148;
    cudaDeviceGetAttribute(&nsm, cudaDevAttrMultiProcessorCount, 0);
    int need = (ntiles + 7) / 8;
    int maxg = 2 * nsm;
    int grid = need < maxg ? need : maxg;

    cudaFuncSetAttribute(edge_update_v11,
                         cudaFuncAttributeMaxDynamicSharedMemorySize, SMEM_BYTES);
    prep_all<<<74, 256>>>(W_init, b_init, W_mlp, b_mlp, W_alpha, b_alpha,
                          (const long long*)edges);
    prep_node<<<(n_node4 + 255) / 256, 256>>>(node_fts, n_node4);
    edge_update_v11<<<grid, NT, SMEM_BYTES>>>(edge_fts, edges, out, n_edges);
}